// round 6
// baseline (speedup 1.0000x reference)
#include <cuda_runtime.h>
#include <cuda_bf16.h>
#include <cstdint>

// Reference is mathematically the identity map (verified rel_err 2.9e-07):
// output (32,1,160000) == input (32,160000). Kernel = 20.48MB D2D copy.
//
// R1-R5: five mechanisms (LDG thin, LDG MLP=8 single wave, CE memcpy, TMA
// bulk, L2-pinned LDG) ALL land at 8.7-8.9us with NOTHING saturated
// (DRAM 30%, L2 25%, issue 3%). Latency is covered (TMA had 128KB/SM in
// flight). => a common per-requester-path throttle caps each mechanism at
// ~2.35 TB/s read.
//
// R6: run the copy-engine path AND the SM path CONCURRENTLY on disjoint
// halves via graph fork-join (event fork from stream 0 -> side stream with
// CE memcpy node, SM kernel node on stream 0, event join). If the caps are
// per-path, aggregate doubles -> ~4.6us. If chip-level, neutral (diagnostic).

#define UNROLL 8

__global__ void __launch_bounds__(256) stft_copy_half(
    const float4* __restrict__ in, float4* __restrict__ out, int n4)
{
    int base = blockIdx.x * (256 * UNROLL) + threadIdx.x;

    if (base + 256 * (UNROLL - 1) < n4) {
        float4 v[UNROLL];
#pragma unroll
        for (int k = 0; k < UNROLL; k++)
            v[k] = in[base + k * 256];
#pragma unroll
        for (int k = 0; k < UNROLL; k++)
            out[base + k * 256] = v[k];
    } else {
#pragma unroll
        for (int k = 0; k < UNROLL; k++) {
            int i = base + k * 256;
            if (i < n4) out[i] = in[i];
        }
    }
}

// Lazy host-side handles (no device memory; identical work every call).
static cudaStream_t g_s2 = nullptr;
static cudaEvent_t g_fork = nullptr, g_join = nullptr;

extern "C" void kernel_launch(void* const* d_in, const int* in_sizes, int n_in,
                              void* d_out, int out_size) {
    if (g_s2 == nullptr) {
        cudaStreamCreateWithFlags(&g_s2, cudaStreamNonBlocking);
        cudaEventCreateWithFlags(&g_fork, cudaEventDisableTiming);
        cudaEventCreateWithFlags(&g_join, cudaEventDisableTiming);
    }

    const float* in = (const float*)d_in[0];
    float* out = (float*)d_out;

    int n = out_size;                    // 5,120,000 floats
    int half = n / 2;                    // 2,560,000 floats (128B aligned)
    int half4 = half >> 2;               // 640,000 float4

    // Fork: side stream joins the capture via event dependency.
    cudaEventRecord(g_fork, 0);
    cudaStreamWaitEvent(g_s2, g_fork, 0);

    // CE path: second half via memcpy node on the side stream.
    cudaMemcpyAsync(out + half, in + half, (size_t)(n - half) * sizeof(float),
                    cudaMemcpyDeviceToDevice, g_s2);

    // SM path: first half via MLP=8 float4 kernel on the capture stream.
    int per_block = 256 * UNROLL;                       // 2048 float4
    int blocks = (half4 + per_block - 1) / per_block;   // 313 blocks
    stft_copy_half<<<blocks, 256>>>((const float4*)in, (float4*)out, half4);

    // Join: capture stream waits for the CE branch.
    cudaEventRecord(g_join, g_s2);
    cudaStreamWaitEvent(0, g_join, 0);
}

// round 7
// speedup vs baseline: 1.1454x; 1.1454x over previous
#include <cuda_runtime.h>
#include <cuda_bf16.h>
#include <cstdint>

// Reference is mathematically the identity map (verified rel_err 2.9e-07):
// output (32,1,160000) == input (32,160000). Kernel = 20.48MB D2D copy.
//
// Measured model (R3 full vs R6 half kernel): T = 4.7us fixed + bytes/10.9TB/s.
// The marginal 10.9 TB/s IS the LTS ceiling (~6300 B/cyc @ ~1.75GHz NAT) --
// the transfer is already optimal; the ~4.7us per-kernel fixed cost
// (launch/ramp/drain, invariant across LDG/TMA/grid 313-5000) dominates.
//
// R6's CE branch was the mistake (CE launch overhead >> copy). R7: fork TWO
// SM kernels on parallel graph branches, each copying a contiguous half.
// Fixed costs overlap; transfer phases share the LTS cap.
// Expected: ~4.7 + 41MB/10.9TB/s ~= 7.3us.

#define UNROLL 8

__global__ void __launch_bounds__(256) stft_copy_span(
    const float4* __restrict__ in, float4* __restrict__ out, int n4)
{
    int base = blockIdx.x * (256 * UNROLL) + threadIdx.x;

    if (base + 256 * (UNROLL - 1) < n4) {
        float4 v[UNROLL];
#pragma unroll
        for (int k = 0; k < UNROLL; k++)
            v[k] = in[base + k * 256];
#pragma unroll
        for (int k = 0; k < UNROLL; k++)
            out[base + k * 256] = v[k];
    } else {
#pragma unroll
        for (int k = 0; k < UNROLL; k++) {
            int i = base + k * 256;
            if (i < n4) out[i] = in[i];
        }
    }
}

// Lazy host-side handles (no device memory; identical captured work per call).
static cudaStream_t g_s2 = nullptr;
static cudaEvent_t g_fork = nullptr, g_join = nullptr;

extern "C" void kernel_launch(void* const* d_in, const int* in_sizes, int n_in,
                              void* d_out, int out_size) {
    if (g_s2 == nullptr) {
        cudaStreamCreateWithFlags(&g_s2, cudaStreamNonBlocking);
        cudaEventCreateWithFlags(&g_fork, cudaEventDisableTiming);
        cudaEventCreateWithFlags(&g_join, cudaEventDisableTiming);
    }

    const float* in = (const float*)d_in[0];
    float* out = (float*)d_out;

    int n = out_size;                 // 5,120,000 floats
    int n4 = n >> 2;                  // 1,280,000 float4 (exact)
    int half4 = n4 / 2;               // 640,000 float4 (128B aligned split)

    int per_block = 256 * UNROLL;                        // 2048 float4
    int blocks = (half4 + per_block - 1) / per_block;    // 313

    // Fork
    cudaEventRecord(g_fork, 0);
    cudaStreamWaitEvent(g_s2, g_fork, 0);

    // Branch A (capture stream): first half
    stft_copy_span<<<blocks, 256>>>((const float4*)in, (float4*)out, half4);

    // Branch B (side stream): second half
    stft_copy_span<<<blocks, 256, 0, g_s2>>>(
        (const float4*)(in) + half4, (float4*)(out) + half4, n4 - half4);

    // Join
    cudaEventRecord(g_join, g_s2);
    cudaStreamWaitEvent(0, g_join, 0);
}